// round 12
// baseline (speedup 1.0000x reference)
#include <cuda_runtime.h>
#include <cstdint>

#define T_SEQ 128
#define BATCH 512
#define DIM   128
#define NQ    8
#define NCH   32   // 4 gates * 8 wires

typedef unsigned long long u64;

__device__ __forceinline__ float tanh_approx(float x) {
    float r;
    asm("tanh.approx.f32 %0, %1;" : "=f"(r) : "f"(x));
    return r;
}
__device__ __forceinline__ void ffma2(u64& acc, u64 a, u64 b) {
    asm("fma.rn.f32x2 %0, %1, %2, %0;" : "+l"(acc) : "l"(a), "l"(b));
}
__device__ __forceinline__ u64 pack2(float lo, float hi) {
    u64 r; asm("mov.b64 %0, {%1, %2};" : "=l"(r) : "f"(lo), "f"(hi)); return r;
}
__device__ __forceinline__ void unpack2(float& lo, float& hi, u64 v) {
    asm("mov.b64 {%0, %1}, %2;" : "=f"(lo), "=f"(hi) : "l"(v));
}

// ---------------------------------------------------------------------------
// Single fused kernel. Block = 128 threads (4 warps), 2 batch rows.
// Phase 1 (all 4 warps): x-projection for both rows, all 128 timesteps, into
//   zs[row][t*32+ch] in shared memory. Warp w: row (w>>1), t-half (w&1).
//   Lane ch owns Wx column ch (64 packed f32x2 regs); x loaded as ulonglong2
//   (naturally packed, zero pack MOVs); 4 independent accumulators.
// Phase 2 (warps 0-1): the PROVEN R4 recurrence loop, one warp per row,
//   z read from smem instead of gmem.
// Quantum layer (analytic): <Z_w> = prod_{k<=w} cos(phi_k) (w>=1),
//                           <Z_0> = prod_{k=1..7} cos(phi_k).
// ---------------------------------------------------------------------------
__global__ void __launch_bounds__(128) qlstm_fused(
    const float* __restrict__ x,
    const float* __restrict__ Wf, const float* __restrict__ bf, const float* __restrict__ thf,
    const float* __restrict__ Wi, const float* __restrict__ bi, const float* __restrict__ thi,
    const float* __restrict__ Wu, const float* __restrict__ bu, const float* __restrict__ thu,
    const float* __restrict__ Wo, const float* __restrict__ bo, const float* __restrict__ tho,
    float* __restrict__ out)
{
    __shared__ __align__(16) float zs[2][T_SEQ * NCH];   // 32 KB

    const int lane = threadIdx.x & 31;
    const int warp = threadIdx.x >> 5;
    const int gate = lane >> 3;
    const int wire = lane & 7;
    const int base = lane & 24;                    // gate*8

    const float* Wg = (gate == 0) ? Wf : (gate == 1) ? Wi : (gate == 2) ? Wu : Wo;
    const float* bg = (gate == 0) ? bf : (gate == 1) ? bi : (gate == 2) ? bu : bo;
    const float* tg = (gate == 0) ? thf : (gate == 1) ? thi : (gate == 2) ? thu : tho;

    // ===================== Phase 1: x-projection =====================
    {
        const int rloc = warp >> 1;                       // 0 or 1
        const int row  = blockIdx.x * 2 + rloc;
        const int t0   = (warp & 1) * 64;                 // timestep half

        // Wx column for this lane's channel: 64 packed pairs
        u64 wxp[64];
        #pragma unroll
        for (int j = 0; j < 64; ++j)
            wxp[j] = pack2(Wg[(2 * j) * NQ + wire],
                           Wg[(2 * j + 1) * NQ + wire]);

        #pragma unroll 1
        for (int tt = 0; tt < 64; ++tt) {
            const int t = t0 + tt;
            const ulonglong2* xt = reinterpret_cast<const ulonglong2*>(
                x + ((size_t)t * BATCH + row) * DIM);

            u64 a0 = 0ull, a1 = 0ull, a2 = 0ull, a3 = 0ull;
            #pragma unroll
            for (int j = 0; j < 8; ++j) {
                ulonglong2 v0 = xt[4 * j + 0];
                ulonglong2 v1 = xt[4 * j + 1];
                ulonglong2 v2 = xt[4 * j + 2];
                ulonglong2 v3 = xt[4 * j + 3];
                ffma2(a0, v0.x, wxp[8 * j + 0]); ffma2(a0, v0.y, wxp[8 * j + 1]);
                ffma2(a1, v1.x, wxp[8 * j + 2]); ffma2(a1, v1.y, wxp[8 * j + 3]);
                ffma2(a2, v2.x, wxp[8 * j + 4]); ffma2(a2, v2.y, wxp[8 * j + 5]);
                ffma2(a3, v3.x, wxp[8 * j + 6]); ffma2(a3, v3.y, wxp[8 * j + 7]);
            }
            float l0, h0_, l1, h1_, l2, h2_, l3, h3_;
            unpack2(l0, h0_, a0); unpack2(l1, h1_, a1);
            unpack2(l2, h2_, a2); unpack2(l3, h3_, a3);
            zs[rloc][t * NCH + lane] = ((l0 + h0_) + (l1 + h1_))
                                     + ((l2 + h2_) + (l3 + h3_));
        }
    }
    __syncthreads();
    if (warp >= 2) return;

    // ===================== Phase 2: recurrence (R4 body) =====================
    const int row = blockIdx.x * 2 + warp;

    float wh0 = Wg[(DIM + 0) * NQ + wire];
    float wh1 = Wg[(DIM + 1) * NQ + wire];
    float wh2 = Wg[(DIM + 2) * NQ + wire];
    float wh3 = Wg[(DIM + 3) * NQ + wire];
    float wh4 = Wg[(DIM + 4) * NQ + wire];
    float wh5 = Wg[(DIM + 5) * NQ + wire];
    float wh6 = Wg[(DIM + 6) * NQ + wire];
    float wh7 = Wg[(DIM + 7) * NQ + wire];

    const float cbias = bg[wire] + tg[wire];
    const bool  isU   = (gate == 2);
    const float aScl  = isU ? 1.0f : 0.5f;
    const float aMul  = isU ? 1.0f : 0.5f;
    const float aAdd  = isU ? 0.0f : 0.5f;

    const bool p0 = (wire & 1) != 0;
    const bool p1 = (wire & 2) != 0;
    const bool p2 = (wire & 4) != 0;

    float h0=0,h1=0,h2=0,h3=0,h4=0,h5=0,h6=0,h7=0;
    float cstate = 0.0f;

    const float* zr = &zs[warp][lane];
    float znext = zr[0];

    float* outw = out + (size_t)row * NQ + wire;   // step stride = BATCH*NQ

    const unsigned FULL = 0xffffffffu;

    #pragma unroll 2
    for (int t = 0; t < T_SEQ; ++t) {
        float zb = znext + cbias;
        int tn = (t + 1 < T_SEQ) ? (t + 1) : (T_SEQ - 1);
        znext = zr[tn * NCH];                       // smem prefetch (lat 29)

        // z = zb + h . wh  (mul + add tree)
        float m0 = h0*wh0, m1 = h1*wh1, m2 = h2*wh2, m3 = h3*wh3;
        float m4 = h4*wh4, m5 = h5*wh5, m6 = h6*wh6, m7 = h7*wh7;
        float a01 = m0+m1, a23 = m2+m3, a45 = m4+m5, a67 = m6+m7;
        float z = ((a01+a23) + (a45+a67)) + zb;

        float c = __cosf(z);

        // allgather segment cosines (8 shfls)
        float cc0 = __shfl_sync(FULL, c, base + 0);
        float cc1 = __shfl_sync(FULL, c, base + 1);
        float cc2 = __shfl_sync(FULL, c, base + 2);
        float cc3 = __shfl_sync(FULL, c, base + 3);
        float cc4 = __shfl_sync(FULL, c, base + 4);
        float cc5 = __shfl_sync(FULL, c, base + 5);
        float cc6 = __shfl_sync(FULL, c, base + 6);
        float cc7 = __shfl_sync(FULL, c, base + 7);

        // prefix products (Sklansky)
        float m01 = cc0*cc1, m23 = cc2*cc3, m45 = cc4*cc5, m67 = cc6*cc7;
        float m0123 = m01*m23, m4567 = m45*m67;
        float P1 = m01;
        float P2 = m01*cc2;
        float P3 = m0123;
        float P4 = m0123*cc4;
        float P5 = m0123*m45;
        float P6 = m0123*(m45*cc6);
        float P7 = m0123*m4567;
        float E0 = (cc1*m23)*m4567;          // prod c1..c7

        // mux by wire bits
        float t0v = p0 ? P1 : E0;
        float t1v = p0 ? P3 : P2;
        float t2v = p0 ? P5 : P4;
        float t3v = p0 ? P7 : P6;
        float u0 = p1 ? t1v : t0v;
        float u1 = p1 ? t3v : t2v;
        float e  = p2 ? u1 : u0;             // <Z_wire>

        // activation: sigmoid via tanh for f,i,o; tanh for u
        float act = fmaf(aMul, tanh_approx(e * aScl), aAdd);

        // gather the four gate values of this wire (4 shfls)
        float fv = __shfl_sync(FULL, act, wire);
        float iv = __shfl_sync(FULL, act, wire + 8);
        float gv = __shfl_sync(FULL, act, wire + 16);
        float ov = __shfl_sync(FULL, act, wire + 24);

        cstate   = fmaf(fv, cstate, iv * gv);
        float hw = ov * tanh_approx(cstate);

        if (lane < 8)
            outw[(size_t)t * (BATCH * NQ)] = hw;     // predicated store

        // broadcast new hx (8 shfls)
        h0 = __shfl_sync(FULL, hw, 0);
        h1 = __shfl_sync(FULL, hw, 1);
        h2 = __shfl_sync(FULL, hw, 2);
        h3 = __shfl_sync(FULL, hw, 3);
        h4 = __shfl_sync(FULL, hw, 4);
        h5 = __shfl_sync(FULL, hw, 5);
        h6 = __shfl_sync(FULL, hw, 6);
        h7 = __shfl_sync(FULL, hw, 7);
    }

    if (lane < 8) {
        const size_t outs_sz = (size_t)T_SEQ * BATCH * NQ;
        float hmy = (wire==0)?h0:(wire==1)?h1:(wire==2)?h2:(wire==3)?h3:
                    (wire==4)?h4:(wire==5)?h5:(wire==6)?h6:h7;
        out[outs_sz + (size_t)row * NQ + wire] = hmy;                          // final hx
        out[outs_sz + (size_t)BATCH * NQ + (size_t)row * NQ + wire] = cstate;  // final cx
    }
}

// ---------------------------------------------------------------------------
// Launch — one kernel, 256 blocks x 128 threads (2 rows per block)
// ---------------------------------------------------------------------------
extern "C" void kernel_launch(void* const* d_in, const int* in_sizes, int n_in,
                              void* d_out, int out_size)
{
    const float* x   = (const float*)d_in[0];
    const float* Wf  = (const float*)d_in[1];
    const float* bf  = (const float*)d_in[2];
    const float* thf = (const float*)d_in[3];
    const float* Wi  = (const float*)d_in[4];
    const float* bi  = (const float*)d_in[5];
    const float* thi = (const float*)d_in[6];
    const float* Wu  = (const float*)d_in[7];
    const float* bu  = (const float*)d_in[8];
    const float* thu = (const float*)d_in[9];
    const float* Wo  = (const float*)d_in[10];
    const float* bo  = (const float*)d_in[11];
    const float* tho = (const float*)d_in[12];
    float* out = (float*)d_out;

    qlstm_fused<<<BATCH / 2, 128>>>(x,
                                    Wf, bf, thf, Wi, bi, thi,
                                    Wu, bu, thu, Wo, bo, tho, out);
}

// round 13
// speedup vs baseline: 1.4081x; 1.4081x over previous
#include <cuda_runtime.h>
#include <cstdint>

#define T_SEQ 128
#define BATCH 512
#define DIM   128
#define NQ    8
#define NCH   32   // 4 gates * 8 wires

typedef unsigned long long u64;

// Scratch: zpre[(t*BATCH+b)*32 + ch] = x_t[b] @ Wx[:,ch], ch = gate*8+wire
__device__ float g_zpre[(size_t)T_SEQ * BATCH * NCH];
// per-timestep completion flags (4 producer blocks per timestep)
__device__ int g_flags[T_SEQ];

__device__ __forceinline__ float tanh_approx(float x) {
    float r;
    asm("tanh.approx.f32 %0, %1;" : "=f"(r) : "f"(x));
    return r;
}
__device__ __forceinline__ void ffma2(u64& acc, u64 a, u64 b) {
    asm("fma.rn.f32x2 %0, %1, %2, %0;" : "+l"(acc) : "l"(a), "l"(b));
}
__device__ __forceinline__ u64 pack2(float lo, float hi) {
    u64 r; asm("mov.b64 %0, {%1, %2};" : "=l"(r) : "f"(lo), "f"(hi)); return r;
}
__device__ __forceinline__ int ld_acquire(const int* p) {
    int v;
    asm volatile("ld.acquire.gpu.s32 %0, [%1];" : "=r"(v) : "l"(p) : "memory");
    return v;
}

// ---------------------------------------------------------------------------
// Reset kernel: zero the flags (graph-replayed before the fused kernel).
// ---------------------------------------------------------------------------
__global__ void qlstm_reset() {
    if (threadIdx.x < T_SEQ) g_flags[threadIdx.x] = 0;
}

// ---------------------------------------------------------------------------
// Fused overlap kernel, 640 blocks x 128 threads.
//   blocks 0..511:  the PROVEN GEMM (block k computes timestep k>>2), then
//                   fence + atomicAdd(g_flags[k>>2]).
//   blocks 512..639: the PROVEN R4 recurrence (1 warp/row), gated by an
//                   amortized acquire-poll of g_flags.
// All 640 blocks are co-resident (smem 33KB -> 6/SM; threads trivially fit),
// so the consumers' spin cannot starve the producers.
// Quantum layer (analytic): <Z_w> = prod_{k<=w} cos(phi_k) (w>=1),
//                           <Z_0> = prod_{k=1..7} cos(phi_k).
// ---------------------------------------------------------------------------
__global__ void __launch_bounds__(128) qlstm_overlap(
    const float* __restrict__ x,
    const float* __restrict__ Wf, const float* __restrict__ bf, const float* __restrict__ thf,
    const float* __restrict__ Wi, const float* __restrict__ bi, const float* __restrict__ thi,
    const float* __restrict__ Wu, const float* __restrict__ bu, const float* __restrict__ thu,
    const float* __restrict__ Wo, const float* __restrict__ bo, const float* __restrict__ tho,
    float* __restrict__ out)
{
    __shared__ __align__(16) float ws[128][32];
    __shared__ float xs[32][129];

    const int tid  = threadIdx.x;
    const int lane = tid & 31;

    if (blockIdx.x < 512) {
        // ===================== GEMM producer (proven body) =====================
        const int row0 = blockIdx.x * 128;

        #pragma unroll 4
        for (int i = tid; i < 128 * 32; i += 128) {
            int k = i >> 5, j = i & 31;
            int g = j >> 3, w = j & 7;
            const float* Wg = (g == 0) ? Wf : (g == 1) ? Wi : (g == 2) ? Wu : Wo;
            ws[k][j] = Wg[k * 8 + w];
        }

        const int c0 = (tid >> 5) * 8;

        u64 acc[4][4];
        #pragma unroll
        for (int r = 0; r < 4; r++)
            #pragma unroll
            for (int q = 0; q < 4; q++) acc[r][q] = 0ull;

        for (int kc = 0; kc < 4; ++kc) {
            __syncthreads();
            #pragma unroll 4
            for (int i = tid; i < 128 * 32; i += 128) {
                int r = i >> 5, kk = i & 31;
                xs[kk][r] = x[(size_t)(row0 + r) * DIM + kc * 32 + kk];
            }
            __syncthreads();

            #pragma unroll
            for (int k = 0; k < 32; ++k) {
                float xv0 = xs[k][lane      ];
                float xv1 = xs[k][lane + 32 ];
                float xv2 = xs[k][lane + 64 ];
                float xv3 = xs[k][lane + 96 ];
                u64 xx0 = pack2(xv0, xv0);
                u64 xx1 = pack2(xv1, xv1);
                u64 xx2 = pack2(xv2, xv2);
                u64 xx3 = pack2(xv3, xv3);
                const u64* wk = reinterpret_cast<const u64*>(&ws[kc * 32 + k][c0]);
                u64 w0 = wk[0], w1 = wk[1], w2 = wk[2], w3 = wk[3];
                ffma2(acc[0][0], xx0, w0); ffma2(acc[0][1], xx0, w1);
                ffma2(acc[0][2], xx0, w2); ffma2(acc[0][3], xx0, w3);
                ffma2(acc[1][0], xx1, w0); ffma2(acc[1][1], xx1, w1);
                ffma2(acc[1][2], xx1, w2); ffma2(acc[1][3], xx1, w3);
                ffma2(acc[2][0], xx2, w0); ffma2(acc[2][1], xx2, w1);
                ffma2(acc[2][2], xx2, w2); ffma2(acc[2][3], xx2, w3);
                ffma2(acc[3][0], xx3, w0); ffma2(acc[3][1], xx3, w1);
                ffma2(acc[3][2], xx3, w2); ffma2(acc[3][3], xx3, w3);
            }
        }

        #pragma unroll
        for (int rr = 0; rr < 4; ++rr) {
            int r = row0 + lane + 32 * rr;
            u64* dst = reinterpret_cast<u64*>(g_zpre + (size_t)r * NCH + c0);
            dst[0] = acc[rr][0]; dst[1] = acc[rr][1];
            dst[2] = acc[rr][2]; dst[3] = acc[rr][3];
        }

        // publish: this block's timestep slice is complete
        __threadfence();
        __syncthreads();
        if (tid == 0)
            atomicAdd(&g_flags[blockIdx.x >> 2], 1);
        return;
    }

    // ===================== Recurrence consumer (proven R4 body) =====================
    const int warp = tid >> 5;
    const int row  = (blockIdx.x - 512) * 4 + warp;   // 0..511
    const int gate = lane >> 3;
    const int wire = lane & 7;
    const int base = lane & 24;                        // gate*8

    const float* Wg = (gate == 0) ? Wf : (gate == 1) ? Wi : (gate == 2) ? Wu : Wo;
    const float* bg = (gate == 0) ? bf : (gate == 1) ? bi : (gate == 2) ? bu : bo;
    const float* tg = (gate == 0) ? thf : (gate == 1) ? thi : (gate == 2) ? thu : tho;

    float wh0 = Wg[(DIM + 0) * NQ + wire];
    float wh1 = Wg[(DIM + 1) * NQ + wire];
    float wh2 = Wg[(DIM + 2) * NQ + wire];
    float wh3 = Wg[(DIM + 3) * NQ + wire];
    float wh4 = Wg[(DIM + 4) * NQ + wire];
    float wh5 = Wg[(DIM + 5) * NQ + wire];
    float wh6 = Wg[(DIM + 6) * NQ + wire];
    float wh7 = Wg[(DIM + 7) * NQ + wire];

    const float cbias = bg[wire] + tg[wire];
    const bool  isU   = (gate == 2);
    const float aScl  = isU ? 1.0f : 0.5f;
    const float aMul  = isU ? 1.0f : 0.5f;
    const float aAdd  = isU ? 0.0f : 0.5f;

    const bool p0 = (wire & 1) != 0;
    const bool p1 = (wire & 2) != 0;
    const bool p2 = (wire & 4) != 0;

    float h0=0,h1=0,h2=0,h3=0,h4=0,h5=0,h6=0,h7=0;
    float cstate = 0.0f;

    const float* zp = g_zpre + (size_t)row * NCH + lane;
    const size_t tstride = (size_t)BATCH * NCH;

    // --- readiness tracking: rt = number of leading timesteps known complete ---
    int rt = 0;
    bool allr = false;
    // need t=0..5 before prefetching through the first poll window
    while (rt < 6) { if (ld_acquire(&g_flags[rt]) == 4) ++rt; }

    float zn0 = zp[0];
    float zn1 = zp[tstride];

    float* outw = out + (size_t)row * NQ + wire;   // step stride = BATCH*NQ

    const unsigned FULL = 0xffffffffu;

    #pragma unroll 2
    for (int t = 0; t < T_SEQ; ++t) {
        // amortized poll: every 4 steps ensure timesteps < t+6 are ready
        if (!allr && (t & 3) == 0) {
            int T = t + 6;
            if (T > T_SEQ) T = T_SEQ;
            while (rt < T) { if (ld_acquire(&g_flags[rt]) == 4) ++rt; }
            if (rt == T_SEQ) allr = true;
        }

        float zb = zn0 + cbias;
        zn0 = zn1;
        int t2 = (t + 2 < T_SEQ) ? (t + 2) : (T_SEQ - 1);
        zn1 = zp[(size_t)t2 * tstride];             // off-chain prefetch

        // z = zb + h . wh  (mul + add tree)
        float m0 = h0*wh0, m1 = h1*wh1, m2 = h2*wh2, m3 = h3*wh3;
        float m4 = h4*wh4, m5 = h5*wh5, m6 = h6*wh6, m7 = h7*wh7;
        float a01 = m0+m1, a23 = m2+m3, a45 = m4+m5, a67 = m6+m7;
        float z = ((a01+a23) + (a45+a67)) + zb;

        float c = __cosf(z);

        // allgather segment cosines (8 shfls)
        float cc0 = __shfl_sync(FULL, c, base + 0);
        float cc1 = __shfl_sync(FULL, c, base + 1);
        float cc2 = __shfl_sync(FULL, c, base + 2);
        float cc3 = __shfl_sync(FULL, c, base + 3);
        float cc4 = __shfl_sync(FULL, c, base + 4);
        float cc5 = __shfl_sync(FULL, c, base + 5);
        float cc6 = __shfl_sync(FULL, c, base + 6);
        float cc7 = __shfl_sync(FULL, c, base + 7);

        // prefix products (Sklansky)
        float m01 = cc0*cc1, m23 = cc2*cc3, m45 = cc4*cc5, m67 = cc6*cc7;
        float m0123 = m01*m23, m4567 = m45*m67;
        float P1 = m01;
        float P2 = m01*cc2;
        float P3 = m0123;
        float P4 = m0123*cc4;
        float P5 = m0123*m45;
        float P6 = m0123*(m45*cc6);
        float P7 = m0123*m4567;
        float E0 = (cc1*m23)*m4567;          // prod c1..c7

        // mux by wire bits
        float t0v = p0 ? P1 : E0;
        float t1v = p0 ? P3 : P2;
        float t2v = p0 ? P5 : P4;
        float t3v = p0 ? P7 : P6;
        float u0 = p1 ? t1v : t0v;
        float u1 = p1 ? t3v : t2v;
        float e  = p2 ? u1 : u0;             // <Z_wire>

        // activation: sigmoid via tanh for f,i,o; tanh for u
        float act = fmaf(aMul, tanh_approx(e * aScl), aAdd);

        // gather the four gate values of this wire (4 shfls)
        float fv = __shfl_sync(FULL, act, wire);
        float iv = __shfl_sync(FULL, act, wire + 8);
        float gv = __shfl_sync(FULL, act, wire + 16);
        float ov = __shfl_sync(FULL, act, wire + 24);

        cstate   = fmaf(fv, cstate, iv * gv);
        float hw = ov * tanh_approx(cstate);

        if (lane < 8)
            outw[(size_t)t * (BATCH * NQ)] = hw;     // predicated store

        // broadcast new hx (8 shfls)
        h0 = __shfl_sync(FULL, hw, 0);
        h1 = __shfl_sync(FULL, hw, 1);
        h2 = __shfl_sync(FULL, hw, 2);
        h3 = __shfl_sync(FULL, hw, 3);
        h4 = __shfl_sync(FULL, hw, 4);
        h5 = __shfl_sync(FULL, hw, 5);
        h6 = __shfl_sync(FULL, hw, 6);
        h7 = __shfl_sync(FULL, hw, 7);
    }

    if (lane < 8) {
        const size_t outs_sz = (size_t)T_SEQ * BATCH * NQ;
        float hmy = (wire==0)?h0:(wire==1)?h1:(wire==2)?h2:(wire==3)?h3:
                    (wire==4)?h4:(wire==5)?h5:(wire==6)?h6:h7;
        out[outs_sz + (size_t)row * NQ + wire] = hmy;                          // final hx
        out[outs_sz + (size_t)BATCH * NQ + (size_t)row * NQ + wire] = cstate;  // final cx
    }
}

// ---------------------------------------------------------------------------
// Launch: reset flags, then one overlapped kernel (512 GEMM + 128 recurrence
// blocks, co-resident).
// ---------------------------------------------------------------------------
extern "C" void kernel_launch(void* const* d_in, const int* in_sizes, int n_in,
                              void* d_out, int out_size)
{
    const float* x   = (const float*)d_in[0];
    const float* Wf  = (const float*)d_in[1];
    const float* bf  = (const float*)d_in[2];
    const float* thf = (const float*)d_in[3];
    const float* Wi  = (const float*)d_in[4];
    const float* bi  = (const float*)d_in[5];
    const float* thi = (const float*)d_in[6];
    const float* Wu  = (const float*)d_in[7];
    const float* bu  = (const float*)d_in[8];
    const float* thu = (const float*)d_in[9];
    const float* Wo  = (const float*)d_in[10];
    const float* bo  = (const float*)d_in[11];
    const float* tho = (const float*)d_in[12];
    float* out = (float*)d_out;

    qlstm_reset<<<1, 128>>>();
    qlstm_overlap<<<512 + 128, 128>>>(x,
                                      Wf, bf, thf, Wi, bi, thi,
                                      Wu, bu, thu, Wo, bo, tho, out);
}